// round 3
// baseline (speedup 1.0000x reference)
#include <cuda_runtime.h>

#define SS 2048
#define RR 384

// ---- device scratch (no allocs allowed) ----
__device__ float g_kv[RR * 16 * SS];     // [r][c][s]; c: 0-7 = k, 8-15 = v
__device__ float g_maskT[RR * SS];       // transposed mask [r][s]
__device__ float g_qpart[RR * 16 * 68];  // per-(r, s-block) partials: 64 P[d], Pmu, Pc
__device__ float g_o[RR * 64];           // attention output per r  [h*8+c]
// LN-folded weights (kernel P)
__device__ float g_AW[16 * 64];          // [c][d] = g[d]*Wkv[d][c]
__device__ float g_S1kv[16];
__device__ float g_bkv[16];
__device__ float g_GW[64 * 64];          // [j][d] = g[d]*Wg[d][j]
__device__ float g_S1g[64];
__device__ float g_bG[64];               // bg[j] + sum_d b[d]*Wg[d][j]
__device__ float g_WoT[64 * 64];         // [d][j] = Wo[j][d]

// ---- packed fp32x2 helpers (Blackwell FFMA2) ----
__device__ __forceinline__ unsigned long long ffma2(unsigned long long a,
                                                    unsigned long long b,
                                                    unsigned long long c) {
    unsigned long long d;
    asm("fma.rn.f32x2 %0, %1, %2, %3;" : "=l"(d) : "l"(a), "l"(b), "l"(c));
    return d;
}
__device__ __forceinline__ float2 upk(unsigned long long v) {
    float2 f; asm("mov.b64 {%0,%1}, %2;" : "=f"(f.x), "=f"(f.y) : "l"(v)); return f;
}
__device__ __forceinline__ unsigned long long pk2(float lo, float hi) {
    unsigned long long r; asm("mov.b64 %0, {%1,%2};" : "=l"(r) : "f"(lo), "f"(hi)); return r;
}

// ---------------------------------------------------------------------------
// Kernel D: transpose mask [S][R] -> [R][S]
// ---------------------------------------------------------------------------
__global__ __launch_bounds__(256) void kernelD(const float* __restrict__ Mmask) {
    __shared__ float t[32][33];
    const int tx = threadIdx.x & 31, ty = threadIdx.x >> 5;  // ty 0..7
    const int r0 = blockIdx.x * 32, s0 = blockIdx.y * 32;
    #pragma unroll
    for (int k = 0; k < 32; k += 8)
        t[ty + k][tx] = Mmask[(s0 + ty + k) * RR + r0 + tx];
    __syncthreads();
    #pragma unroll
    for (int k = 0; k < 32; k += 8)
        g_maskT[(r0 + ty + k) * SS + s0 + tx] = t[tx][ty + k];
}

// ---------------------------------------------------------------------------
// Kernel P: fold LayerNorm gamma/beta into all weight matrices (tiny, once)
// ---------------------------------------------------------------------------
__global__ __launch_bounds__(256) void kernelP(
    const float* __restrict__ lng, const float* __restrict__ lnb,
    const float* __restrict__ Wk, const float* __restrict__ Wv,
    const float* __restrict__ Wg, const float* __restrict__ bg,
    const float* __restrict__ Wo)
{
    const int tid = threadIdx.x;
    for (int i = tid; i < 16 * 64; i += 256) {
        int c = i >> 6, d = i & 63;
        float w = (c < 8) ? Wk[d * 8 + c] : Wv[d * 8 + c - 8];
        g_AW[i] = lng[d] * w;
    }
    for (int i = tid; i < 64 * 64; i += 256) {
        int a = i >> 6, b = i & 63;
        g_GW[i]  = lng[b] * Wg[b * 64 + a];   // [j=a][d=b]
        g_WoT[i] = Wo[b * 64 + a];            // [d=a][j=b]
    }
    __syncthreads();
    if (tid < 16) {
        float s1 = 0.f, bb = 0.f;
        for (int d = 0; d < 64; ++d) {
            s1 += g_AW[tid * 64 + d];
            float w = (tid < 8) ? Wk[d * 8 + tid] : Wv[d * 8 + tid - 8];
            bb += lnb[d] * w;
        }
        g_S1kv[tid] = s1; g_bkv[tid] = bb;
    }
    if (tid >= 64 && tid < 128) {
        int j = tid - 64;
        float s1 = 0.f, bb = 0.f;
        for (int d = 0; d < 64; ++d) {
            s1 += g_GW[j * 64 + d];
            bb += lnb[d] * Wg[d * 64 + j];
        }
        g_S1g[j] = s1; g_bG[j] = bg[j] + bb;
    }
}

// ---------------------------------------------------------------------------
// Kernel A: rows-in-lanes LN (folded) + k/v projection + masked-q partials
// grid (16, 384), 128 threads; each thread owns one (s,r) row
// ---------------------------------------------------------------------------
__global__ __launch_bounds__(128) void kernelA(const float* __restrict__ M) {
    __shared__ __align__(16) float stage[4][32][68];
    __shared__ __align__(16) float sAW[16][68];
    __shared__ float sS1[16], sbk[16];
    __shared__ float sQ[4][68];
    const int tid = threadIdx.x, w = tid >> 5, t = tid & 31;
    const int r = blockIdx.y;
    const int srow = blockIdx.x * 128 + w * 32;

    for (int i = tid; i < 16 * 64; i += 128) { int c = i >> 6, d = i & 63; sAW[c][d] = g_AW[i]; }
    if (tid < 16) { sS1[tid] = g_S1kv[tid]; sbk[tid] = g_bkv[tid]; }
    __syncthreads();

    const int cr = t >> 4, cc = (t & 15) * 4;
    #pragma unroll
    for (int i = 0; i < 16; ++i) {
        int rr = i * 2 + cr;
        *(float4*)&stage[w][rr][cc] =
            *(const float4*)&M[(((srow + rr) * RR) + r) * 64 + cc];
    }
    __syncwarp();

    unsigned long long xp[32];
    {
        const ulonglong2* rp = (const ulonglong2*)&stage[w][t][0];
        #pragma unroll
        for (int i = 0; i < 16; ++i) { ulonglong2 v = rp[i]; xp[2 * i] = v.x; xp[2 * i + 1] = v.y; }
    }
    float sum = 0.f, sq = 0.f;
    #pragma unroll
    for (int i = 0; i < 32; ++i) { float2 f = upk(xp[i]); sum += f.x + f.y; sq += f.x * f.x + f.y * f.y; }
    const float mu = sum * (1.f / 64.f);
    const float rstd = rsqrtf(sq * (1.f / 64.f) - mu * mu + 1e-5f);
    const int s = srow + t;
    const float mk = g_maskT[r * SS + s];

    // k/v projection (LN folded)
    #pragma unroll
    for (int c = 0; c < 16; ++c) {
        const ulonglong2* wp_ = (const ulonglong2*)&sAW[c][0];
        unsigned long long a0 = 0ull, a1 = 0ull;
        #pragma unroll
        for (int i = 0; i < 16; ++i) {
            ulonglong2 v = wp_[i];
            a0 = ffma2(xp[2 * i], v.x, a0);
            a1 = ffma2(xp[2 * i + 1], v.y, a1);
        }
        float2 f0 = upk(a0), f1 = upk(a1);
        float dot = f0.x + f0.y + f1.x + f1.y;
        g_kv[((r * 16 + c) * SS) + s] = rstd * (dot - mu * sS1[c]) + sbk[c];
    }

    // masked-query partial rows -> reuse tile, then column-reduce
    {
        const float mkr = mk * rstd;
        const unsigned long long mp = pk2(mkr, mkr);
        float4* qr = (float4*)&stage[w][t][0];
        #pragma unroll
        for (int i = 0; i < 16; ++i) {
            float2 a = upk(ffma2(xp[2 * i], mp, 0ull));
            float2 b = upk(ffma2(xp[2 * i + 1], mp, 0ull));
            qr[i] = make_float4(a.x, a.y, b.x, b.y);
        }
        stage[w][t][64] = mkr * mu;  // Pmu contribution
        stage[w][t][65] = mk;        // Pc contribution
    }
    __syncwarp();
    {
        float ax = 0.f, ay = 0.f;
        #pragma unroll
        for (int rr = 0; rr < 32; ++rr) {
            float2 v = *(const float2*)&stage[w][rr][2 * t];
            ax += v.x; ay += v.y;
        }
        sQ[w][2 * t] = ax; sQ[w][2 * t + 1] = ay;
        if (t < 2) {
            float e = 0.f;
            #pragma unroll
            for (int rr = 0; rr < 32; ++rr) e += stage[w][rr][64 + t];
            sQ[w][64 + t] = e;
        }
    }
    __syncthreads();
    if (tid < 66) {
        float a = sQ[0][tid] + sQ[1][tid] + sQ[2][tid] + sQ[3][tid];
        g_qpart[(r * 16 + blockIdx.x) * 68 + tid] = a;
    }
}

// ---------------------------------------------------------------------------
// Kernel B: pooled q, two-pass streaming softmax over S (no logits buffer)
// grid (384), 256 threads; k/v stream from L2, accumulators in registers
// ---------------------------------------------------------------------------
__global__ __launch_bounds__(256) void kernelB(
    const float* __restrict__ Wq, const float* __restrict__ lng,
    const float* __restrict__ lnb)
{
    __shared__ float sqa[68];
    __shared__ float sq[64];
    __shared__ float smax[8];
    __shared__ float red[8][80];
    const int tid = threadIdx.x, w = tid >> 5, t = tid & 31, r = blockIdx.x;

    if (tid < 66) {
        float a = 0.f;
        #pragma unroll
        for (int c = 0; c < 16; ++c) a += g_qpart[(r * 16 + c) * 68 + tid];
        sqa[tid] = a;
    }
    __syncthreads();
    if (tid < 64) {
        float Pmu = sqa[64], Pc = sqa[65];
        sqa[tid] = (lng[tid] * (sqa[tid] - Pmu) + lnb[tid] * Pc) / (Pc + 1e-10f);
    }
    __syncthreads();
    if (tid < 64) {
        float acc = 0.f;
        #pragma unroll
        for (int d = 0; d < 64; ++d) acc += sqa[d] * Wq[d * 64 + tid];
        sq[tid] = acc * 0.35355339059327373f;  // * C^-0.5
    }
    __syncthreads();

    // pass 1: per-head max
    float mx[8];
    #pragma unroll
    for (int h = 0; h < 8; ++h) mx[h] = -3.0e38f;
    for (int s = tid; s < SS; s += 256) {
        float kk[8];
        #pragma unroll
        for (int c = 0; c < 8; ++c) kk[c] = g_kv[((r * 16 + c) * SS) + s];
        float bias = 1e9f * (g_maskT[r * SS + s] - 1.f);
        #pragma unroll
        for (int h = 0; h < 8; ++h) {
            float lg = bias;
            #pragma unroll
            for (int c = 0; c < 8; ++c) lg += sq[h * 8 + c] * kk[c];
            mx[h] = fmaxf(mx[h], lg);
        }
    }
    #pragma unroll
    for (int h = 0; h < 8; ++h) {
        #pragma unroll
        for (int o = 16; o > 0; o >>= 1) mx[h] = fmaxf(mx[h], __shfl_xor_sync(0xffffffffu, mx[h], o));
    }
    if (t < 8) red[w][t] = mx[t];
    __syncthreads();
    if (tid < 8) {
        float m = red[0][tid];
        #pragma unroll
        for (int ww = 1; ww < 8; ++ww) m = fmaxf(m, red[ww][tid]);
        smax[tid] = m;
    }
    __syncthreads();

    // pass 2: exp + weighted-v accumulation in registers
    float Z[8];
    float acc[64];
    #pragma unroll
    for (int h = 0; h < 8; ++h) Z[h] = 0.f;
    #pragma unroll
    for (int i = 0; i < 64; ++i) acc[i] = 0.f;
    for (int s = tid; s < SS; s += 256) {
        float kk[8], vv[8];
        #pragma unroll
        for (int c = 0; c < 8; ++c) kk[c] = g_kv[((r * 16 + c) * SS) + s];
        #pragma unroll
        for (int c = 0; c < 8; ++c) vv[c] = g_kv[((r * 16 + 8 + c) * SS) + s];
        float bias = 1e9f * (g_maskT[r * SS + s] - 1.f);
        #pragma unroll
        for (int h = 0; h < 8; ++h) {
            float lg = bias;
            #pragma unroll
            for (int c = 0; c < 8; ++c) lg += sq[h * 8 + c] * kk[c];
            float e = __expf(lg - smax[h]);
            Z[h] += e;
            #pragma unroll
            for (int c = 0; c < 8; ++c) acc[h * 8 + c] += e * vv[c];
        }
    }
    // hierarchical reduction of 72 values
    #pragma unroll
    for (int i = 0; i < 64; ++i) {
        float v = acc[i];
        #pragma unroll
        for (int o = 16; o > 0; o >>= 1) v += __shfl_xor_sync(0xffffffffu, v, o);
        if (t == 0) red[w][i] = v;
    }
    #pragma unroll
    for (int h = 0; h < 8; ++h) {
        float v = Z[h];
        #pragma unroll
        for (int o = 16; o > 0; o >>= 1) v += __shfl_xor_sync(0xffffffffu, v, o);
        if (t == 0) red[w][64 + h] = v;
    }
    __syncthreads();
    if (tid < 72) {
        float v = 0.f;
        #pragma unroll
        for (int ww = 0; ww < 8; ++ww) v += red[ww][tid];
        red[0][tid] = v;
    }
    __syncthreads();
    if (tid < 64) g_o[r * 64 + tid] = red[0][tid] / red[0][64 + (tid >> 3)];
}

// ---------------------------------------------------------------------------
// Kernel C (hot): rows-in-lanes, folded-LN gate GEMV + output GEMV, FFMA2
// ghat staged through smem scratch so gate/out register peaks never overlap
// grid (8, 384), 128 threads; 2 subtiles of 128 rows per block
// ---------------------------------------------------------------------------
__global__ __launch_bounds__(128) void kernelC(
    const float* __restrict__ M, const float* __restrict__ bo,
    float* __restrict__ outp)
{
    extern __shared__ __align__(16) float dyn[];
    float* stage = dyn;                         // [4][32][68]
    float* scr   = dyn + 4 * 32 * 68;           // [4][32][68] ghat scratch
    float* sGW   = dyn + 2 * 4 * 32 * 68;       // [64][68]
    float* sWoT  = sGW + 64 * 68;               // [64][68]
    float* so    = sWoT + 64 * 68;              // [64]
    float* sS1g  = so + 64;                     // [64]
    float* sbG   = sS1g + 64;                   // [64]
    float* sbo   = sbG + 64;                    // [64]
    const int tid = threadIdx.x, w = tid >> 5, t = tid & 31;
    const int r = blockIdx.y;

    for (int i = tid; i < 4096; i += 128) {
        int j = i >> 6, d = i & 63;
        sGW[j * 68 + d]  = g_GW[i];
        sWoT[j * 68 + d] = g_WoT[i];
    }
    if (tid < 64) {
        so[tid] = g_o[r * 64 + tid];
        sS1g[tid] = g_S1g[tid]; sbG[tid] = g_bG[tid]; sbo[tid] = bo[tid];
    }
    __syncthreads();

    float* tile = stage + w * 32 * 68;
    float* grow = scr + w * 32 * 68 + t * 68;
    const int cr = t >> 4, cc = (t & 15) * 4;

    for (int sub = 0; sub < 2; ++sub) {
        const int srow = blockIdx.x * 256 + sub * 128 + w * 32;
        #pragma unroll
        for (int i = 0; i < 16; ++i) {
            int rr = i * 2 + cr;
            *(float4*)&tile[rr * 68 + cc] =
                *(const float4*)&M[(((srow + rr) * RR) + r) * 64 + cc];
        }
        __syncwarp();

        // ---- gate phase: only xp lives in registers ----
        {
            unsigned long long xp[32];
            {
                const ulonglong2* rp = (const ulonglong2*)&tile[t * 68];
                #pragma unroll
                for (int i = 0; i < 16; ++i) { ulonglong2 v = rp[i]; xp[2 * i] = v.x; xp[2 * i + 1] = v.y; }
            }
            float sum = 0.f, sq = 0.f;
            #pragma unroll
            for (int i = 0; i < 32; ++i) { float2 f = upk(xp[i]); sum += f.x + f.y; sq += f.x * f.x + f.y * f.y; }
            const float mu = sum * (1.f / 64.f);
            const float rstd = rsqrtf(sq * (1.f / 64.f) - mu * mu + 1e-5f);

            #pragma unroll
            for (int jp = 0; jp < 32; ++jp) {
                const ulonglong2* wa = (const ulonglong2*)&sGW[(2 * jp) * 68];
                const ulonglong2* wb = (const ulonglong2*)&sGW[(2 * jp + 1) * 68];
                unsigned long long a0 = 0ull, a1 = 0ull, b0 = 0ull, b1 = 0ull;
                #pragma unroll
                for (int i = 0; i < 16; ++i) {
                    ulonglong2 va = wa[i], vb = wb[i];
                    a0 = ffma2(xp[2 * i], va.x, a0); a1 = ffma2(xp[2 * i + 1], va.y, a1);
                    b0 = ffma2(xp[2 * i], vb.x, b0); b1 = ffma2(xp[2 * i + 1], vb.y, b1);
                }
                float2 fa0 = upk(a0), fa1 = upk(a1), fb0 = upk(b0), fb1 = upk(b1);
                float da = fa0.x + fa0.y + fa1.x + fa1.y;
                float db = fb0.x + fb0.y + fb1.x + fb1.y;
                float aga = rstd * (da - mu * sS1g[2 * jp])     + sbG[2 * jp];
                float agb = rstd * (db - mu * sS1g[2 * jp + 1]) + sbG[2 * jp + 1];
                float ga = 1.f / (1.f + __expf(-aga));
                float gb = 1.f / (1.f + __expf(-agb));
                float2 oo = *(const float2*)&so[2 * jp];
                *(float2*)&grow[2 * jp] = make_float2(ga * oo.x, gb * oo.y);
            }
        }
        __syncwarp();

        // ---- out phase: only gp lives in registers; x re-read from tile ----
        {
            unsigned long long gp[32];
            {
                const ulonglong2* gr = (const ulonglong2*)grow;
                #pragma unroll
                for (int i = 0; i < 16; ++i) { ulonglong2 v = gr[i]; gp[2 * i] = v.x; gp[2 * i + 1] = v.y; }
            }
            #pragma unroll
            for (int dp = 0; dp < 32; ++dp) {
                const ulonglong2* wa = (const ulonglong2*)&sWoT[(2 * dp) * 68];
                const ulonglong2* wb = (const ulonglong2*)&sWoT[(2 * dp + 1) * 68];
                unsigned long long a0 = 0ull, a1 = 0ull, b0 = 0ull, b1 = 0ull;
                #pragma unroll
                for (int i = 0; i < 16; ++i) {
                    ulonglong2 va = wa[i], vb = wb[i];
                    a0 = ffma2(gp[2 * i], va.x, a0); a1 = ffma2(gp[2 * i + 1], va.y, a1);
                    b0 = ffma2(gp[2 * i], vb.x, b0); b1 = ffma2(gp[2 * i + 1], vb.y, b1);
                }
                float2 fa0 = upk(a0), fa1 = upk(a1), fb0 = upk(b0), fb1 = upk(b1);
                float2 xr = *(const float2*)&tile[t * 68 + 2 * dp];
                float o0 = fa0.x + fa0.y + fa1.x + fa1.y + sbo[2 * dp]     + xr.x;
                float o1 = fb0.x + fb0.y + fb1.x + fb1.y + sbo[2 * dp + 1] + xr.y;
                *(float2*)&tile[t * 68 + 2 * dp] = make_float2(o0, o1);
            }
        }
        __syncwarp();
        #pragma unroll
        for (int i = 0; i < 16; ++i) {
            int rr = i * 2 + cr;
            *(float4*)&outp[(((srow + rr) * RR) + r) * 64 + cc] =
                *(const float4*)&tile[rr * 68 + cc];
        }
        __syncwarp();
    }
}

// ---------------------------------------------------------------------------
extern "C" void kernel_launch(void* const* d_in, const int* in_sizes, int n_in,
                              void* d_out, int out_size)
{
    (void)in_sizes; (void)n_in; (void)out_size;
    const float* M    = (const float*)d_in[0];
    const float* mask = (const float*)d_in[1];
    const float* ln_g = (const float*)d_in[2];
    const float* ln_b = (const float*)d_in[3];
    const float* Wq   = (const float*)d_in[4];
    const float* Wk   = (const float*)d_in[5];
    const float* Wv   = (const float*)d_in[6];
    const float* Wg   = (const float*)d_in[7];
    const float* bg   = (const float*)d_in[8];
    const float* Wo   = (const float*)d_in[9];
    const float* bo   = (const float*)d_in[10];
    float* outp = (float*)d_out;

    const int smemC = (2 * 4 * 32 * 68 + 2 * 64 * 68 + 4 * 64) * 4;  // 105472 B
    cudaFuncSetAttribute(kernelC, cudaFuncAttributeMaxDynamicSharedMemorySize, smemC);

    kernelD<<<dim3(12, 64), 256>>>(mask);
    kernelP<<<1, 256>>>(ln_g, ln_b, Wk, Wv, Wg, bg, Wo);
    kernelA<<<dim3(16, 384), 128>>>(M);
    kernelB<<<384, 256>>>(Wq, ln_g, ln_b);
    kernelC<<<dim3(8, 384), 128, smemC>>>(M, bo, outp);
}

// round 6
// speedup vs baseline: 1.0996x; 1.0996x over previous
#include <cuda_runtime.h>

#define SS 2048
#define RR 384

typedef unsigned long long ull;

// ---- device scratch (no allocs allowed) ----
__device__ float g_kv[RR * 16 * SS];     // [r][c][s]; c: 0-7 = k, 8-15 = v
__device__ float g_maskT[RR * SS];       // transposed mask [r][s]
__device__ float g_qpart[RR * 16 * 68];  // per-(r, s-block) partials
__device__ float g_o[RR * 64];           // attention output per r  [h*8+c]
__device__ float2 g_stats[RR * SS];      // per-row (mu, rstd) for kernelC
// LN-folded weights (kernel P)
__device__ float g_AW[16 * 64];          // [c][d] = g[d]*Wkv[d][c]
__device__ float g_S1kv[16];
__device__ float g_bkv[16];
__device__ float g_GW[64 * 64];          // [j][d] = g[d]*Wg[d][j]
__device__ float g_S1g[64];
__device__ float g_bG[64];               // bg[j] + sum_d b[d]*Wg[d][j]
__device__ float g_WoT[64 * 64];         // [d][j] = Wo[j][d]

// ---- packed fp32x2 helpers (Blackwell FFMA2) ----
__device__ __forceinline__ ull ffma2(ull a, ull b, ull c) {
    ull d;
    asm("fma.rn.f32x2 %0, %1, %2, %3;" : "=l"(d) : "l"(a), "l"(b), "l"(c));
    return d;
}
__device__ __forceinline__ float2 upk(ull v) {
    float2 f; asm("mov.b64 {%0,%1}, %2;" : "=f"(f.x), "=f"(f.y) : "l"(v)); return f;
}
__device__ __forceinline__ ull pk2(float lo, float hi) {
    ull r; asm("mov.b64 %0, {%1,%2};" : "=l"(r) : "f"(lo), "f"(hi)); return r;
}

// ---------------------------------------------------------------------------
// Kernel D: transpose mask [S][R] -> [R][S]
// ---------------------------------------------------------------------------
__global__ __launch_bounds__(256) void kernelD(const float* __restrict__ Mmask) {
    __shared__ float t[32][33];
    const int tx = threadIdx.x & 31, ty = threadIdx.x >> 5;
    const int r0 = blockIdx.x * 32, s0 = blockIdx.y * 32;
    #pragma unroll
    for (int k = 0; k < 32; k += 8)
        t[ty + k][tx] = Mmask[(s0 + ty + k) * RR + r0 + tx];
    __syncthreads();
    #pragma unroll
    for (int k = 0; k < 32; k += 8)
        g_maskT[(r0 + ty + k) * SS + s0 + tx] = t[tx][ty + k];
}

// ---------------------------------------------------------------------------
// Kernel P: fold LayerNorm gamma/beta into all weight matrices (tiny, once)
// ---------------------------------------------------------------------------
__global__ __launch_bounds__(256) void kernelP(
    const float* __restrict__ lng, const float* __restrict__ lnb,
    const float* __restrict__ Wk, const float* __restrict__ Wv,
    const float* __restrict__ Wg, const float* __restrict__ bg,
    const float* __restrict__ Wo)
{
    const int tid = threadIdx.x;
    for (int i = tid; i < 16 * 64; i += 256) {
        int c = i >> 6, d = i & 63;
        float w = (c < 8) ? Wk[d * 8 + c] : Wv[d * 8 + c - 8];
        g_AW[i] = lng[d] * w;
    }
    for (int i = tid; i < 64 * 64; i += 256) {
        int a = i >> 6, b = i & 63;
        g_GW[i]  = lng[b] * Wg[b * 64 + a];   // [j=a][d=b]
        g_WoT[i] = Wo[b * 64 + a];            // [d=a][j=b]
    }
    __syncthreads();
    if (tid < 16) {
        float s1 = 0.f, bb = 0.f;
        for (int d = 0; d < 64; ++d) {
            s1 += g_AW[tid * 64 + d];
            float w = (tid < 8) ? Wk[d * 8 + tid] : Wv[d * 8 + tid - 8];
            bb += lnb[d] * w;
        }
        g_S1kv[tid] = s1; g_bkv[tid] = bb;
    }
    if (tid >= 64 && tid < 128) {
        int j = tid - 64;
        float s1 = 0.f, bb = 0.f;
        for (int d = 0; d < 64; ++d) {
            s1 += g_GW[j * 64 + d];
            bb += lnb[d] * Wg[d * 64 + j];
        }
        g_S1g[j] = s1; g_bG[j] = bg[j] + bb;
    }
}

// ---------------------------------------------------------------------------
// Kernel A: rows-in-lanes LN (folded) + k/v projection + masked-q partials
// also stores per-row (mu, rstd) for kernelC
// ---------------------------------------------------------------------------
__global__ __launch_bounds__(128) void kernelA(const float* __restrict__ M) {
    __shared__ __align__(16) float stage[4][32][68];
    __shared__ __align__(16) float sAW[16][68];
    __shared__ float sS1[16], sbk[16];
    __shared__ float sQ[4][68];
    const int tid = threadIdx.x, w = tid >> 5, t = tid & 31;
    const int r = blockIdx.y;
    const int srow = blockIdx.x * 128 + w * 32;

    for (int i = tid; i < 16 * 64; i += 128) { int c = i >> 6, d = i & 63; sAW[c][d] = g_AW[i]; }
    if (tid < 16) { sS1[tid] = g_S1kv[tid]; sbk[tid] = g_bkv[tid]; }
    __syncthreads();

    const int cr = t >> 4, cc = (t & 15) * 4;
    #pragma unroll
    for (int i = 0; i < 16; ++i) {
        int rr = i * 2 + cr;
        *(float4*)&stage[w][rr][cc] =
            *(const float4*)&M[(((srow + rr) * RR) + r) * 64 + cc];
    }
    __syncwarp();

    ull xp[32];
    {
        const ulonglong2* rp = (const ulonglong2*)&stage[w][t][0];
        #pragma unroll
        for (int i = 0; i < 16; ++i) { ulonglong2 v = rp[i]; xp[2 * i] = v.x; xp[2 * i + 1] = v.y; }
    }
    float sum = 0.f, sq = 0.f;
    #pragma unroll
    for (int i = 0; i < 32; ++i) { float2 f = upk(xp[i]); sum += f.x + f.y; sq += f.x * f.x + f.y * f.y; }
    const float mu = sum * (1.f / 64.f);
    const float rstd = rsqrtf(sq * (1.f / 64.f) - mu * mu + 1e-5f);
    const int s = srow + t;
    const float mk = g_maskT[r * SS + s];
    g_stats[r * SS + s] = make_float2(mu, rstd);

    // k/v projection (LN folded)
    #pragma unroll
    for (int c = 0; c < 16; ++c) {
        const ulonglong2* wp_ = (const ulonglong2*)&sAW[c][0];
        ull a0 = 0ull, a1 = 0ull;
        #pragma unroll
        for (int i = 0; i < 16; ++i) {
            ulonglong2 v = wp_[i];
            a0 = ffma2(xp[2 * i], v.x, a0);
            a1 = ffma2(xp[2 * i + 1], v.y, a1);
        }
        float2 f0 = upk(a0), f1 = upk(a1);
        float dot = f0.x + f0.y + f1.x + f1.y;
        g_kv[((r * 16 + c) * SS) + s] = rstd * (dot - mu * sS1[c]) + sbk[c];
    }

    // masked-query partial rows -> reuse tile, then column-reduce
    {
        const float mkr = mk * rstd;
        const ull mp = pk2(mkr, mkr);
        float4* qr = (float4*)&stage[w][t][0];
        #pragma unroll
        for (int i = 0; i < 16; ++i) {
            float2 a = upk(ffma2(xp[2 * i], mp, 0ull));
            float2 b = upk(ffma2(xp[2 * i + 1], mp, 0ull));
            qr[i] = make_float4(a.x, a.y, b.x, b.y);
        }
        stage[w][t][64] = mkr * mu;  // Pmu contribution
        stage[w][t][65] = mk;        // Pc contribution
    }
    __syncwarp();
    {
        float ax = 0.f, ay = 0.f;
        #pragma unroll
        for (int rr = 0; rr < 32; ++rr) {
            float2 v = *(const float2*)&stage[w][rr][2 * t];
            ax += v.x; ay += v.y;
        }
        sQ[w][2 * t] = ax; sQ[w][2 * t + 1] = ay;
        if (t < 2) {
            float e = 0.f;
            #pragma unroll
            for (int rr = 0; rr < 32; ++rr) e += stage[w][rr][64 + t];
            sQ[w][64 + t] = e;
        }
    }
    __syncthreads();
    if (tid < 66) {
        float a = sQ[0][tid] + sQ[1][tid] + sQ[2][tid] + sQ[3][tid];
        g_qpart[(r * 16 + blockIdx.x) * 68 + tid] = a;
    }
}

// ---------------------------------------------------------------------------
// Kernel B: pooled q, two-pass streaming softmax over S (no logits buffer)
// ---------------------------------------------------------------------------
__global__ __launch_bounds__(256) void kernelB(
    const float* __restrict__ Wq, const float* __restrict__ lng,
    const float* __restrict__ lnb)
{
    __shared__ float sqa[68];
    __shared__ float sq[64];
    __shared__ float smax[8];
    __shared__ float red[8][80];
    const int tid = threadIdx.x, w = tid >> 5, t = tid & 31, r = blockIdx.x;

    if (tid < 66) {
        float a = 0.f;
        #pragma unroll
        for (int c = 0; c < 16; ++c) a += g_qpart[(r * 16 + c) * 68 + tid];
        sqa[tid] = a;
    }
    __syncthreads();
    if (tid < 64) {
        float Pmu = sqa[64], Pc = sqa[65];
        sqa[tid] = (lng[tid] * (sqa[tid] - Pmu) + lnb[tid] * Pc) / (Pc + 1e-10f);
    }
    __syncthreads();
    if (tid < 64) {
        float acc = 0.f;
        #pragma unroll
        for (int d = 0; d < 64; ++d) acc += sqa[d] * Wq[d * 64 + tid];
        sq[tid] = acc * 0.35355339059327373f;
    }
    __syncthreads();

    // pass 1: per-head max
    float mx[8];
    #pragma unroll
    for (int h = 0; h < 8; ++h) mx[h] = -3.0e38f;
    for (int s = tid; s < SS; s += 256) {
        float kk[8];
        #pragma unroll
        for (int c = 0; c < 8; ++c) kk[c] = g_kv[((r * 16 + c) * SS) + s];
        float bias = 1e9f * (g_maskT[r * SS + s] - 1.f);
        #pragma unroll
        for (int h = 0; h < 8; ++h) {
            float lg = bias;
            #pragma unroll
            for (int c = 0; c < 8; ++c) lg += sq[h * 8 + c] * kk[c];
            mx[h] = fmaxf(mx[h], lg);
        }
    }
    #pragma unroll
    for (int h = 0; h < 8; ++h) {
        #pragma unroll
        for (int o = 16; o > 0; o >>= 1) mx[h] = fmaxf(mx[h], __shfl_xor_sync(0xffffffffu, mx[h], o));
    }
    if (t < 8) red[w][t] = mx[t];
    __syncthreads();
    if (tid < 8) {
        float m = red[0][tid];
        #pragma unroll
        for (int ww = 1; ww < 8; ++ww) m = fmaxf(m, red[ww][tid]);
        smax[tid] = m;
    }
    __syncthreads();

    // pass 2: exp + weighted-v accumulation
    float Z[8];
    float acc[64];
    #pragma unroll
    for (int h = 0; h < 8; ++h) Z[h] = 0.f;
    #pragma unroll
    for (int i = 0; i < 64; ++i) acc[i] = 0.f;
    for (int s = tid; s < SS; s += 256) {
        float kk[8], vv[8];
        #pragma unroll
        for (int c = 0; c < 8; ++c) kk[c] = g_kv[((r * 16 + c) * SS) + s];
        #pragma unroll
        for (int c = 0; c < 8; ++c) vv[c] = g_kv[((r * 16 + 8 + c) * SS) + s];
        float bias = 1e9f * (g_maskT[r * SS + s] - 1.f);
        #pragma unroll
        for (int h = 0; h < 8; ++h) {
            float lg = bias;
            #pragma unroll
            for (int c = 0; c < 8; ++c) lg += sq[h * 8 + c] * kk[c];
            float e = __expf(lg - smax[h]);
            Z[h] += e;
            #pragma unroll
            for (int c = 0; c < 8; ++c) acc[h * 8 + c] += e * vv[c];
        }
    }
    #pragma unroll
    for (int i = 0; i < 64; ++i) {
        float v = acc[i];
        #pragma unroll
        for (int o = 16; o > 0; o >>= 1) v += __shfl_xor_sync(0xffffffffu, v, o);
        if (t == 0) red[w][i] = v;
    }
    #pragma unroll
    for (int h = 0; h < 8; ++h) {
        float v = Z[h];
        #pragma unroll
        for (int o = 16; o > 0; o >>= 1) v += __shfl_xor_sync(0xffffffffu, v, o);
        if (t == 0) red[w][64 + h] = v;
    }
    __syncthreads();
    if (tid < 72) {
        float v = 0.f;
        #pragma unroll
        for (int ww = 0; ww < 8; ++ww) v += red[ww][tid];
        red[0][tid] = v;
    }
    __syncthreads();
    if (tid < 64) g_o[r * 64 + tid] = red[0][tid] / red[0][64 + (tid >> 3)];
}

// ---------------------------------------------------------------------------
// Kernel C (hot): column-per-lane decomposition. Weights live in REGISTERS,
// x/ghat rows are broadcast from smem (16 LDS.128/row). LN stats precomputed.
// grid (8, 384), 128 threads (4 warps), 2 subtiles of 32 rows per warp.
// ---------------------------------------------------------------------------
__global__ __launch_bounds__(128) void kernelC(
    const float* __restrict__ M, const float* __restrict__ bo,
    float* __restrict__ outp)
{
    extern __shared__ __align__(16) float dyn[];  // [4 warps][2 tiles][32*68]
    const int tid = threadIdx.x, w = tid >> 5, t = tid & 31;
    const int r = blockIdx.y;
    float* xt = dyn + (w * 2 + 0) * (32 * 68);
    float* gt = dyn + (w * 2 + 1) * (32 * 68);

    // per-lane constants: lane owns gate cols {2t,2t+1} and out cols {2t,2t+1}
    const float2 s1g = *(const float2*)&g_S1g[2 * t];
    const float2 bG2 = *(const float2*)&g_bG[2 * t];
    const float2 oo  = *(const float2*)&g_o[r * 64 + 2 * t];
    const float2 bo2 = *(const float2*)&bo[2 * t];
    const int cr = t >> 4, cc = (t & 15) * 4;

    ull gw[64];  // current-phase weights: [0..31] = col 2t, [32..63] = col 2t+1

    for (int sub = 0; sub < 2; ++sub) {
        const int srow = blockIdx.x * 256 + sub * 128 + w * 32;
        // stage x tile
        #pragma unroll
        for (int i = 0; i < 16; ++i) {
            int rr = i * 2 + cr;
            *(float4*)&xt[rr * 68 + cc] =
                *(const float4*)&M[(((srow + rr) * RR) + r) * 64 + cc];
        }
        *(float2*)&xt[t * 68 + 66] = g_stats[r * SS + srow + t];
        __syncwarp();

        // ---- gate phase ----
        {
            const ulonglong2* p0 = (const ulonglong2*)(g_GW + (2 * t) * 64);
            const ulonglong2* p1 = (const ulonglong2*)(g_GW + (2 * t + 1) * 64);
            #pragma unroll
            for (int i = 0; i < 16; ++i) {
                ulonglong2 v0 = p0[i], v1 = p1[i];
                gw[2 * i] = v0.x; gw[2 * i + 1] = v0.y;
                gw[32 + 2 * i] = v1.x; gw[32 + 2 * i + 1] = v1.y;
            }
        }
        for (int row = 0; row < 32; ++row) {
            const ulonglong2* xr = (const ulonglong2*)&xt[row * 68];
            ull a00 = 0ull, a01 = 0ull, a10 = 0ull, a11 = 0ull;
            #pragma unroll
            for (int i = 0; i < 16; ++i) {
                ulonglong2 xv = xr[i];
                a00 = ffma2(xv.x, gw[2 * i], a00);
                a01 = ffma2(xv.y, gw[2 * i + 1], a01);
                a10 = ffma2(xv.x, gw[32 + 2 * i], a10);
                a11 = ffma2(xv.y, gw[32 + 2 * i + 1], a11);
            }
            float2 st = *(const float2*)&xt[row * 68 + 66];
            float2 f;
            f = upk(a00); float d0 = f.x + f.y;
            f = upk(a01); d0 += f.x + f.y;
            f = upk(a10); float d1 = f.x + f.y;
            f = upk(a11); d1 += f.x + f.y;
            float ag0 = st.y * (d0 - st.x * s1g.x) + bG2.x;
            float ag1 = st.y * (d1 - st.x * s1g.y) + bG2.y;
            float g0 = oo.x / (1.f + __expf(-ag0));
            float g1 = oo.y / (1.f + __expf(-ag1));
            *(float2*)&gt[row * 68 + 2 * t] = make_float2(g0, g1);
        }
        __syncwarp();

        // ---- out phase ----
        {
            const ulonglong2* p0 = (const ulonglong2*)(g_WoT + (2 * t) * 64);
            const ulonglong2* p1 = (const ulonglong2*)(g_WoT + (2 * t + 1) * 64);
            #pragma unroll
            for (int i = 0; i < 16; ++i) {
                ulonglong2 v0 = p0[i], v1 = p1[i];
                gw[2 * i] = v0.x; gw[2 * i + 1] = v0.y;
                gw[32 + 2 * i] = v1.x; gw[32 + 2 * i + 1] = v1.y;
            }
        }
        for (int row = 0; row < 32; ++row) {
            const ulonglong2* gr = (const ulonglong2*)&gt[row * 68];
            ull a00 = 0ull, a01 = 0ull, a10 = 0ull, a11 = 0ull;
            #pragma unroll
            for (int i = 0; i < 16; ++i) {
                ulonglong2 gv = gr[i];
                a00 = ffma2(gv.x, gw[2 * i], a00);
                a01 = ffma2(gv.y, gw[2 * i + 1], a01);
                a10 = ffma2(gv.x, gw[32 + 2 * i], a10);
                a11 = ffma2(gv.y, gw[32 + 2 * i + 1], a11);
            }
            float2 f;
            f = upk(a00); float d0 = f.x + f.y;
            f = upk(a01); d0 += f.x + f.y;
            f = upk(a10); float d1 = f.x + f.y;
            f = upk(a11); d1 += f.x + f.y;
            float2 xres = *(const float2*)&xt[row * 68 + 2 * t];
            float2 ov = make_float2(d0 + bo2.x + xres.x, d1 + bo2.y + xres.y);
            *(float2*)&outp[(((srow + row) * RR) + r) * 64 + 2 * t] = ov;
        }
        __syncwarp();  // xt/gt reuse barrier before next subtile
    }
}

// ---------------------------------------------------------------------------
extern "C" void kernel_launch(void* const* d_in, const int* in_sizes, int n_in,
                              void* d_out, int out_size)
{
    (void)in_sizes; (void)n_in; (void)out_size;
    const float* M    = (const float*)d_in[0];
    const float* mask = (const float*)d_in[1];
    const float* ln_g = (const float*)d_in[2];
    const float* ln_b = (const float*)d_in[3];
    const float* Wq   = (const float*)d_in[4];
    const float* Wk   = (const float*)d_in[5];
    const float* Wv   = (const float*)d_in[6];
    const float* Wg   = (const float*)d_in[7];
    const float* bg   = (const float*)d_in[8];
    const float* Wo   = (const float*)d_in[9];
    const float* bo   = (const float*)d_in[10];
    float* outp = (float*)d_out;

    const int smemC = 4 * 2 * 32 * 68 * 4;  // 69632 B
    cudaFuncSetAttribute(kernelC, cudaFuncAttributeMaxDynamicSharedMemorySize, smemC);

    kernelD<<<dim3(12, 64), 256>>>(mask);
    kernelP<<<1, 256>>>(ln_g, ln_b, Wk, Wv, Wg, bg, Wo);
    kernelA<<<dim3(16, 384), 128>>>(M);
    kernelB<<<384, 256>>>(Wq, ln_g, ln_b);
    kernelC<<<dim3(8, 384), 128, smemC>>>(M, bo, outp);
}